// round 13
// baseline (speedup 1.0000x reference)
#include <cuda_runtime.h>
#include <cuda_fp16.h>
#include <math.h>

#define NTOK 16384
#define DDIM 1024
#define HDIM 4096
#define NEXP 8
#define PROJD 256
#define CAP 12288
#define CLAMP_MAXV 4.605170185988091f

#define BMT 256
#define BNT 128
#define BKT 64
#define NTHR 512
#define A_BYTES 32768        /* 256 rows * 128B */
#define B_BYTES 16384        /* 128 rows * 128B */
#define OFF_B A_BYTES
#define STAGE (A_BYTES + B_BYTES)   /* 49152 */
#define SMEM_DYN (2 * STAGE)        /* 98304 */

// ---------------- device scratch ----------------
__device__ float g_P[NTOK * PROJD];
__device__ float g_simn[PROJD * NEXP];
__device__ int   g_perm[NEXP * CAP];
__device__ int   g_pos[NTOK * 2];
__device__ float g_gate[NTOK * 2];
__device__ int   g_cursor[NEXP];
__device__ __half g_xh[(size_t)NTOK * DDIM];
__device__ __half g_w1t[(size_t)NEXP * HDIM * DDIM];   // [E][H][D]
__device__ __half g_w2t[(size_t)NEXP * DDIM * HDIM];   // [E][D][H]
__device__ __half g_Hh[(size_t)NEXP * CAP * HDIM];
__device__ float g_F[(size_t)NEXP * CAP * DDIM];

// ---------------- helpers ----------------
__device__ __forceinline__ unsigned smem_u32(const void* p) {
    unsigned a;
    asm("{ .reg .u64 t; cvta.to.shared.u64 t, %1; cvt.u32.u64 %0, t; }" : "=r"(a) : "l"(p));
    return a;
}
#define CPA(dst, src) asm volatile("cp.async.cg.shared.global [%0], [%1], 16;" :: "r"(dst), "l"(src))
#define CPA_COMMIT()  asm volatile("cp.async.commit_group;" ::: "memory")
#define CPA_WAIT1()   asm volatile("cp.async.wait_group 1;" ::: "memory")
#define CPA_WAIT0()   asm volatile("cp.async.wait_group 0;" ::: "memory")
#define LDSM4(R, A) asm volatile("ldmatrix.sync.aligned.m8n8.x4.shared.b16 {%0,%1,%2,%3}, [%4];" \
    : "=r"((R)[0]), "=r"((R)[1]), "=r"((R)[2]), "=r"((R)[3]) : "r"(A))

__device__ __forceinline__ void mma16816(float* c, const unsigned* a, const unsigned* b) {
    asm volatile(
        "mma.sync.aligned.m16n8k16.row.col.f32.f16.f16.f32 "
        "{%0,%1,%2,%3}, {%4,%5,%6,%7}, {%8,%9}, {%0,%1,%2,%3};"
        : "+f"(c[0]), "+f"(c[1]), "+f"(c[2]), "+f"(c[3])
        : "r"(a[0]), "r"(a[1]), "r"(a[2]), "r"(a[3]), "r"(b[0]), "r"(b[1]));
}
// 64 fp16 per row = 128B line; 16B chunks 0..7, chunk XOR'd by row -> conflict-free
__device__ __forceinline__ unsigned swa(int r, int ch) {
    return (unsigned)(r * 128 + ((ch ^ (r & 7)) << 4));
}

// ---------------- small kernels ----------------
__global__ void init_kernel() { if (threadIdx.x < NEXP) g_cursor[threadIdx.x] = 0; }

__global__ void simn_kernel(const float* __restrict__ sim) {
    int e = threadIdx.x;
    if (e < NEXP) {
        float s = 0.f;
        for (int j = 0; j < PROJD; j++) { float v = sim[j * NEXP + e]; s += v * v; }
        float inv = 1.f / fmaxf(sqrtf(s), 1e-12f);
        for (int j = 0; j < PROJD; j++) g_simn[j * NEXP + e] = sim[j * NEXP + e] * inv;
    }
}

__global__ void gating_kernel(const float* __restrict__ P, const float* __restrict__ temp) {
    __shared__ float ssim[PROJD * NEXP];
    for (int i = threadIdx.x; i < PROJD * NEXP; i += blockDim.x) ssim[i] = g_simn[i];
    __syncthreads();
    int tok = (blockIdx.x * blockDim.x + threadIdx.x) >> 5;
    int lane = threadIdx.x & 31;
    if (tok >= NTOK) return;
    const float* row = P + (size_t)tok * PROJD;
    float dot[NEXP];
#pragma unroll
    for (int e = 0; e < NEXP; e++) dot[e] = 0.f;
    float ss = 0.f;
#pragma unroll
    for (int i = 0; i < PROJD / 32; i++) {
        float p = row[lane + 32 * i];
        ss += p * p;
        const float* sr = ssim + (lane + 32 * i) * NEXP;
#pragma unroll
        for (int e = 0; e < NEXP; e++) dot[e] += p * sr[e];
    }
#pragma unroll
    for (int off = 16; off; off >>= 1) {
        ss += __shfl_down_sync(0xffffffffu, ss, off);
#pragma unroll
        for (int e = 0; e < NEXP; e++) dot[e] += __shfl_down_sync(0xffffffffu, dot[e], off);
    }
    if (lane == 0) {
        float scale = expf(fminf(temp[0], CLAMP_MAXV));
        float inv = 1.f / fmaxf(sqrtf(ss), 1e-12f);
        float lg[NEXP];
#pragma unroll
        for (int e = 0; e < NEXP; e++) lg[e] = dot[e] * inv * scale;
        int e0 = 0;
#pragma unroll
        for (int e = 1; e < NEXP; e++) if (lg[e] > lg[e0]) e0 = e;
        int e1 = (e0 == 0) ? 1 : 0;
#pragma unroll
        for (int e = 0; e < NEXP; e++) if (e != e0 && lg[e] > lg[e1]) e1 = e;
        float ex = expf(lg[e1] - lg[e0]);
        float den = 1.f + ex;
        int p0 = atomicAdd(&g_cursor[e0], 1); p0 = min(p0, CAP - 1);
        g_perm[e0 * CAP + p0] = tok;
        g_pos[tok * 2 + 0] = e0 * CAP + p0;
        g_gate[tok * 2 + 0] = 1.f / den;
        int p1 = atomicAdd(&g_cursor[e1], 1); p1 = min(p1, CAP - 1);
        g_perm[e1 * CAP + p1] = tok;
        g_pos[tok * 2 + 1] = e1 * CAP + p1;
        g_gate[tok * 2 + 1] = ex / den;
    }
}

__global__ void conv_x_kernel(const float* __restrict__ src, int n4) {
    int i = blockIdx.x * blockDim.x + threadIdx.x;
    if (i >= n4) return;
    float4 v = ((const float4*)src)[i];
    __half2 a = __floats2half2_rn(v.x, v.y);
    __half2 b = __floats2half2_rn(v.z, v.w);
    ((uint2*)g_xh)[i] = make_uint2(*(unsigned*)&a, *(unsigned*)&b);
}

// W [E][R][C] fp32 -> T [E][C][R] fp16  (T must be a cudaGetSymbolAddress pointer!)
__global__ void conv_wt_kernel(const float* __restrict__ W, __half* __restrict__ T, int R, int C) {
    __shared__ float tile[32][33];
    int e = blockIdx.z, r0 = blockIdx.y * 32, c0 = blockIdx.x * 32;
    const float* Wp = W + (size_t)e * R * C;
    for (int i = threadIdx.y; i < 32; i += 8)
        tile[i][threadIdx.x] = Wp[(size_t)(r0 + i) * C + c0 + threadIdx.x];
    __syncthreads();
    for (int i = threadIdx.y; i < 32; i += 8)
        T[((size_t)e * C + c0 + i) * R + r0 + threadIdx.x] = __float2half_rn(tile[threadIdx.x][i]);
}

// fp32 SGEMM for gating projection (exact selection)
__global__ __launch_bounds__(256, 2)
void gemm_p(const float* __restrict__ A, const float* __restrict__ Bw,
            const float* __restrict__ bias, float* __restrict__ C) {
    const int K = DDIM, N = PROJD;
    const int mt = blockIdx.y, nt = blockIdx.x;
    __shared__ float As[8][128], Bs[8][128];
    const int tid = threadIdx.x;
    const int aRow = tid >> 1, aK = (tid & 1) * 4;
    const int bK = tid >> 5, bN = (tid & 31) * 4;
    const float* aPtr = A + (size_t)(mt * 128 + aRow) * K + aK;
    const float* bPtr = Bw + (size_t)bK * N + nt * 128 + bN;
    const int tr = tid >> 4, tc = tid & 15;
    float acc[8][8];
#pragma unroll
    for (int i = 0; i < 8; i++)
#pragma unroll
        for (int j = 0; j < 8; j++) acc[i][j] = 0.f;
    float4 ra = *(const float4*)aPtr;
    float4 rb = *(const float4*)bPtr;
    for (int kt = 0; kt < K / 8; kt++) {
        As[aK][aRow] = ra.x; As[aK + 1][aRow] = ra.y; As[aK + 2][aRow] = ra.z; As[aK + 3][aRow] = ra.w;
        *(float4*)&Bs[bK][bN] = rb;
        __syncthreads();
        if (kt + 1 < K / 8) {
            ra = *(const float4*)(aPtr + (size_t)(kt + 1) * 8);
            rb = *(const float4*)(bPtr + (size_t)(kt + 1) * 8 * N);
        }
#pragma unroll
        for (int k = 0; k < 8; k++) {
            float4 a0 = *(const float4*)&As[k][tr * 8];
            float4 a1 = *(const float4*)&As[k][tr * 8 + 4];
            float4 b0 = *(const float4*)&Bs[k][tc * 8];
            float4 b1 = *(const float4*)&Bs[k][tc * 8 + 4];
            float ar[8] = {a0.x, a0.y, a0.z, a0.w, a1.x, a1.y, a1.z, a1.w};
            float br[8] = {b0.x, b0.y, b0.z, b0.w, b1.x, b1.y, b1.z, b1.w};
#pragma unroll
            for (int i = 0; i < 8; i++)
#pragma unroll
                for (int j = 0; j < 8; j++) acc[i][j] += ar[i] * br[j];
        }
        __syncthreads();
    }
#pragma unroll
    for (int i = 0; i < 8; i++) {
        float* cp = C + (size_t)(mt * 128 + tr * 8 + i) * N + nt * 128 + tc * 8;
#pragma unroll
        for (int j = 0; j < 8; j++) cp[j] = acc[i][j] + bias[nt * 128 + tc * 8 + j];
    }
}

// ---------------- HMMA grouped GEMM (fp16, fp32 acc, BKT=64, 512 threads, 16 warps 4x4) ----------------
// MODE 1: H = gelu(x[perm] @ W1t^T + b1) -> fp16   MODE 2: F = H @ W2t^T + b2 -> fp32
template <int MODE>
__global__ void __launch_bounds__(NTHR)
moe_mma(const float* __restrict__ bias) {
    constexpr int K  = (MODE == 1) ? DDIM : HDIM;
    constexpr int NB = (MODE == 1) ? HDIM : DDIM;
    constexpr int NK = K / BKT;
    const int z = blockIdx.z, mt = blockIdx.y, nt = blockIdx.x;
    const int cnt = min(g_cursor[z], CAP);
    if (mt * BMT >= cnt) return;

    extern __shared__ __align__(128) char smem[];
    const unsigned sb = smem_u32(smem);
    const int tid = threadIdx.x, wid = tid >> 5, lane = tid & 31;

    // ---- load mapping ----
    // A: 256 rows x 128B; thread -> row tid>>1, 64B half (tid&1): 4 cpa
    // B: 128 rows x 128B; thread -> row tid>>2, 32B quarter (tid&3): 2 cpa
    const int arow = tid >> 1;
    const int acb = (tid & 1) * 4;           // chunk base 0 or 4
    const int brow = tid >> 2;
    const int bcb = (tid & 3) * 2;           // chunk base 0,2,4,6
    size_t aOff;
    {
        int r = min(mt * BMT + arow, cnt - 1);
        if (MODE == 1) aOff = (size_t)g_perm[z * CAP + r] * DDIM;
        else           aOff = ((size_t)z * CAP + r) * (size_t)HDIM;
    }
    const size_t bOff = ((size_t)z * NB + nt * BNT + brow) * (size_t)K;
    const __half* gA = (MODE == 1) ? g_xh : g_Hh;
    const __half* gB = (MODE == 1) ? g_w1t : g_w2t;

#define LOADC(cc, ss) do { \
        const unsigned st_ = sb + (ss) * STAGE; \
        const int ka_ = (cc) * BKT + acb * 8; \
        const int kb_ = (cc) * BKT + bcb * 8; \
        _Pragma("unroll") \
        for (int j = 0; j < 4; j++) \
            CPA(st_ + swa(arow, acb + j), gA + aOff + ka_ + 8 * j); \
        _Pragma("unroll") \
        for (int j = 0; j < 2; j++) \
            CPA(st_ + OFF_B + swa(brow, bcb + j), gB + bOff + kb_ + 8 * j); \
        CPA_COMMIT(); \
    } while (0)

    // ---- compute mapping: 16 warps as 4(M) x 4(N); warp tile 64x32 ----
    const int m0 = (wid & 3) * 64;
    const int n0 = (wid >> 2) * 32;
    const int rA = ((lane >> 3) & 1) * 8 + (lane & 7);
    const int cA = lane >> 4;
    const int rB = (lane >> 4) * 8 + (lane & 7);
    const int cB = (lane >> 3) & 1;

    float acc[4][4][4];
#pragma unroll
    for (int f = 0; f < 4; f++)
#pragma unroll
        for (int g = 0; g < 4; g++)
#pragma unroll
            for (int q = 0; q < 4; q++) acc[f][g][q] = 0.f;

    LOADC(0, 0);
    for (int c = 0; c < NK; c++) {
        const int s = c & 1;
        if (c + 1 < NK) { LOADC(c + 1, s ^ 1); CPA_WAIT1(); }
        else CPA_WAIT0();
        __syncthreads();
        const unsigned st = sb + s * STAGE;
#pragma unroll
        for (int kk = 0; kk < 4; kk++) {
            unsigned ah[4][4], bf[4][2];
#pragma unroll
            for (int f = 0; f < 4; f++)
                LDSM4(ah[f], st + swa(m0 + f * 16 + rA, kk * 2 + cA));
#pragma unroll
            for (int j = 0; j < 2; j++) {
                unsigned q[4];
                LDSM4(q, st + OFF_B + swa(n0 + j * 16 + rB, kk * 2 + cB));
                bf[2 * j][0] = q[0]; bf[2 * j][1] = q[1];
                bf[2 * j + 1][0] = q[2]; bf[2 * j + 1][1] = q[3];
            }
#pragma unroll
            for (int f = 0; f < 4; f++)
#pragma unroll
                for (int g = 0; g < 4; g++)
                    mma16816(acc[f][g], ah[f], bf[g]);
        }
        __syncthreads();
    }

    // ---- epilogue ----
    const float* bptr = bias + (size_t)z * NB + nt * BNT;
#pragma unroll
    for (int f = 0; f < 4; f++) {
#pragma unroll
        for (int h = 0; h < 2; h++) {
            const int mg = mt * BMT + m0 + f * 16 + (lane >> 2) + 8 * h;
            if (mg < cnt) {
                const size_t rowg = (size_t)z * CAP + mg;
#pragma unroll
                for (int g = 0; g < 4; g++) {
                    const int nc = n0 + g * 8 + (lane & 3) * 2;
                    float v0 = acc[f][g][2 * h + 0] + __ldg(bptr + nc);
                    float v1 = acc[f][g][2 * h + 1] + __ldg(bptr + nc + 1);
                    if (MODE == 1) {
                        v0 = 0.5f * v0 * (1.0f + erff(v0 * 0.70710678118654752f));
                        v1 = 0.5f * v1 * (1.0f + erff(v1 * 0.70710678118654752f));
                        __half2 hv = __floats2half2_rn(v0, v1);
                        *(unsigned*)(g_Hh + rowg * HDIM + nt * BNT + nc) = *(unsigned*)&hv;
                    } else {
                        *(float2*)(g_F + rowg * DDIM + nt * BNT + nc) = make_float2(v0, v1);
                    }
                }
            }
        }
    }
#undef LOADC
}

__global__ void final_kernel(const float* __restrict__ x, float* __restrict__ out) {
    int idx = blockIdx.x * blockDim.x + threadIdx.x;
    int n = idx >> 8, c = idx & 255;
    float4 xv = ((const float4*)x)[idx];
    int p0 = g_pos[n * 2], p1 = g_pos[n * 2 + 1];
    float gg0 = g_gate[n * 2], gg1 = g_gate[n * 2 + 1];
    const float4* F4 = (const float4*)g_F;
    float4 f0 = F4[(size_t)p0 * 256 + c];
    float4 f1 = F4[(size_t)p1 * 256 + c];
    ((float4*)out)[idx] = make_float4(xv.x + gg0 * f0.x + gg1 * f1.x,
                                      xv.y + gg0 * f0.y + gg1 * f1.y,
                                      xv.z + gg0 * f0.z + gg1 * f1.z,
                                      xv.w + gg0 * f0.w + gg1 * f1.w);
}

// ---------------- launch ----------------
extern "C" void kernel_launch(void* const* d_in, const int* in_sizes, int n_in,
                              void* d_out, int out_size) {
    const float* x    = (const float*)d_in[0];
    const float* Wp   = (const float*)d_in[1];
    const float* bp   = (const float*)d_in[2];
    const float* sim  = (const float*)d_in[3];
    const float* temp = (const float*)d_in[4];
    const float* W1   = (const float*)d_in[5];
    const float* b1   = (const float*)d_in[6];
    const float* W2   = (const float*)d_in[7];
    const float* b2   = (const float*)d_in[8];
    float* out = (float*)d_out;

    cudaFuncSetAttribute(moe_mma<1>, cudaFuncAttributeMaxDynamicSharedMemorySize, SMEM_DYN);
    cudaFuncSetAttribute(moe_mma<2>, cudaFuncAttributeMaxDynamicSharedMemorySize, SMEM_DYN);

    // device addresses for any symbol passed as a HOST-side kernel argument
    void *pP = nullptr, *pw1 = nullptr, *pw2 = nullptr;
    cudaGetSymbolAddress(&pP, g_P);
    cudaGetSymbolAddress(&pw1, g_w1t);
    cudaGetSymbolAddress(&pw2, g_w2t);

    init_kernel<<<1, 32>>>();
    simn_kernel<<<1, 32>>>(sim);
    gemm_p<<<dim3(PROJD / 128, NTOK / 128), 256>>>(x, Wp, bp, (float*)pP);
    gating_kernel<<<(NTOK * 32) / 256, 256>>>((const float*)pP, temp);

    conv_x_kernel<<<(NTOK * DDIM / 4) / 256, 256>>>(x, NTOK * DDIM / 4);
    conv_wt_kernel<<<dim3(HDIM / 32, DDIM / 32, NEXP), dim3(32, 8)>>>(W1, (__half*)pw1, DDIM, HDIM);
    conv_wt_kernel<<<dim3(DDIM / 32, HDIM / 32, NEXP), dim3(32, 8)>>>(W2, (__half*)pw2, HDIM, DDIM);

    moe_mma<1><<<dim3(HDIM / BNT, CAP / BMT, NEXP), NTHR, SMEM_DYN>>>(b1);
    moe_mma<2><<<dim3(DDIM / BNT, CAP / BMT, NEXP), NTHR, SMEM_DYN>>>(b2);

    final_kernel<<<(NTOK * DDIM / 4) / 256, 256>>>(x, out);
}

// round 14
// speedup vs baseline: 1.1240x; 1.1240x over previous
#include <cuda_runtime.h>
#include <cuda_fp16.h>
#include <math.h>

#define NTOK 16384
#define DDIM 1024
#define HDIM 4096
#define NEXP 8
#define PROJD 256
#define CAP 12288
#define CLAMP_MAXV 4.605170185988091f

#define BMT 256
#define BNT 128
#define BKT 64
#define A_BYTES 32768        /* 256 rows * 128B */
#define B_BYTES 16384        /* 128 rows * 128B */
#define OFF_B A_BYTES
#define STAGE (A_BYTES + B_BYTES)   /* 49152 */
#define NSTAGE 3
#define SMEM_DYN (NSTAGE * STAGE)   /* 147456 */

// ---------------- device scratch ----------------
__device__ float g_P[NTOK * PROJD];
__device__ float g_simn[PROJD * NEXP];
__device__ int   g_perm[NEXP * CAP];
__device__ int   g_pos[NTOK * 2];
__device__ float g_gate[NTOK * 2];
__device__ int   g_cursor[NEXP];
__device__ __half g_xh[(size_t)NTOK * DDIM];
__device__ __half g_w1t[(size_t)NEXP * HDIM * DDIM];   // [E][H][D]
__device__ __half g_w2t[(size_t)NEXP * DDIM * HDIM];   // [E][D][H]
__device__ __half g_Hh[(size_t)NEXP * CAP * HDIM];
__device__ float g_F[(size_t)NEXP * CAP * DDIM];

// ---------------- helpers ----------------
__device__ __forceinline__ unsigned smem_u32(const void* p) {
    unsigned a;
    asm("{ .reg .u64 t; cvta.to.shared.u64 t, %1; cvt.u32.u64 %0, t; }" : "=r"(a) : "l"(p));
    return a;
}
#define CPA(dst, src) asm volatile("cp.async.cg.shared.global [%0], [%1], 16;" :: "r"(dst), "l"(src))
#define CPA_COMMIT()  asm volatile("cp.async.commit_group;" ::: "memory")
#define CPA_WAIT1()   asm volatile("cp.async.wait_group 1;" ::: "memory")
#define CPA_WAIT0()   asm volatile("cp.async.wait_group 0;" ::: "memory")
#define LDSM4(R, A) asm volatile("ldmatrix.sync.aligned.m8n8.x4.shared.b16 {%0,%1,%2,%3}, [%4];" \
    : "=r"((R)[0]), "=r"((R)[1]), "=r"((R)[2]), "=r"((R)[3]) : "r"(A))

__device__ __forceinline__ void mma16816(float* c, const unsigned* a, const unsigned* b) {
    asm volatile(
        "mma.sync.aligned.m16n8k16.row.col.f32.f16.f16.f32 "
        "{%0,%1,%2,%3}, {%4,%5,%6,%7}, {%8,%9}, {%0,%1,%2,%3};"
        : "+f"(c[0]), "+f"(c[1]), "+f"(c[2]), "+f"(c[3])
        : "r"(a[0]), "r"(a[1]), "r"(a[2]), "r"(a[3]), "r"(b[0]), "r"(b[1]));
}
// 64 fp16 per row = 128B line; 16B chunks 0..7, chunk XOR'd by row -> conflict-free
__device__ __forceinline__ unsigned swa(int r, int ch) {
    return (unsigned)(r * 128 + ((ch ^ (r & 7)) << 4));
}

// ---------------- small kernels ----------------
__global__ void init_kernel() { if (threadIdx.x < NEXP) g_cursor[threadIdx.x] = 0; }

__global__ void simn_kernel(const float* __restrict__ sim) {
    int e = threadIdx.x;
    if (e < NEXP) {
        float s = 0.f;
        for (int j = 0; j < PROJD; j++) { float v = sim[j * NEXP + e]; s += v * v; }
        float inv = 1.f / fmaxf(sqrtf(s), 1e-12f);
        for (int j = 0; j < PROJD; j++) g_simn[j * NEXP + e] = sim[j * NEXP + e] * inv;
    }
}

__global__ void gating_kernel(const float* __restrict__ P, const float* __restrict__ temp) {
    __shared__ float ssim[PROJD * NEXP];
    for (int i = threadIdx.x; i < PROJD * NEXP; i += blockDim.x) ssim[i] = g_simn[i];
    __syncthreads();
    int tok = (blockIdx.x * blockDim.x + threadIdx.x) >> 5;
    int lane = threadIdx.x & 31;
    if (tok >= NTOK) return;
    const float* row = P + (size_t)tok * PROJD;
    float dot[NEXP];
#pragma unroll
    for (int e = 0; e < NEXP; e++) dot[e] = 0.f;
    float ss = 0.f;
#pragma unroll
    for (int i = 0; i < PROJD / 32; i++) {
        float p = row[lane + 32 * i];
        ss += p * p;
        const float* sr = ssim + (lane + 32 * i) * NEXP;
#pragma unroll
        for (int e = 0; e < NEXP; e++) dot[e] += p * sr[e];
    }
#pragma unroll
    for (int off = 16; off; off >>= 1) {
        ss += __shfl_down_sync(0xffffffffu, ss, off);
#pragma unroll
        for (int e = 0; e < NEXP; e++) dot[e] += __shfl_down_sync(0xffffffffu, dot[e], off);
    }
    if (lane == 0) {
        float scale = expf(fminf(temp[0], CLAMP_MAXV));
        float inv = 1.f / fmaxf(sqrtf(ss), 1e-12f);
        float lg[NEXP];
#pragma unroll
        for (int e = 0; e < NEXP; e++) lg[e] = dot[e] * inv * scale;
        int e0 = 0;
#pragma unroll
        for (int e = 1; e < NEXP; e++) if (lg[e] > lg[e0]) e0 = e;
        int e1 = (e0 == 0) ? 1 : 0;
#pragma unroll
        for (int e = 0; e < NEXP; e++) if (e != e0 && lg[e] > lg[e1]) e1 = e;
        float ex = expf(lg[e1] - lg[e0]);
        float den = 1.f + ex;
        int p0 = atomicAdd(&g_cursor[e0], 1); p0 = min(p0, CAP - 1);
        g_perm[e0 * CAP + p0] = tok;
        g_pos[tok * 2 + 0] = e0 * CAP + p0;
        g_gate[tok * 2 + 0] = 1.f / den;
        int p1 = atomicAdd(&g_cursor[e1], 1); p1 = min(p1, CAP - 1);
        g_perm[e1 * CAP + p1] = tok;
        g_pos[tok * 2 + 1] = e1 * CAP + p1;
        g_gate[tok * 2 + 1] = ex / den;
    }
}

__global__ void conv_x_kernel(const float* __restrict__ src, int n4) {
    int i = blockIdx.x * blockDim.x + threadIdx.x;
    if (i >= n4) return;
    float4 v = ((const float4*)src)[i];
    __half2 a = __floats2half2_rn(v.x, v.y);
    __half2 b = __floats2half2_rn(v.z, v.w);
    ((uint2*)g_xh)[i] = make_uint2(*(unsigned*)&a, *(unsigned*)&b);
}

// W [E][R][C] fp32 -> T [E][C][R] fp16  (T must be a cudaGetSymbolAddress pointer!)
__global__ void conv_wt_kernel(const float* __restrict__ W, __half* __restrict__ T, int R, int C) {
    __shared__ float tile[32][33];
    int e = blockIdx.z, r0 = blockIdx.y * 32, c0 = blockIdx.x * 32;
    const float* Wp = W + (size_t)e * R * C;
    for (int i = threadIdx.y; i < 32; i += 8)
        tile[i][threadIdx.x] = Wp[(size_t)(r0 + i) * C + c0 + threadIdx.x];
    __syncthreads();
    for (int i = threadIdx.y; i < 32; i += 8)
        T[((size_t)e * C + c0 + i) * R + r0 + threadIdx.x] = __float2half_rn(tile[threadIdx.x][i]);
}

// fp32 SGEMM for gating projection (exact selection)
__global__ __launch_bounds__(256, 2)
void gemm_p(const float* __restrict__ A, const float* __restrict__ Bw,
            const float* __restrict__ bias, float* __restrict__ C) {
    const int K = DDIM, N = PROJD;
    const int mt = blockIdx.y, nt = blockIdx.x;
    __shared__ float As[8][128], Bs[8][128];
    const int tid = threadIdx.x;
    const int aRow = tid >> 1, aK = (tid & 1) * 4;
    const int bK = tid >> 5, bN = (tid & 31) * 4;
    const float* aPtr = A + (size_t)(mt * 128 + aRow) * K + aK;
    const float* bPtr = Bw + (size_t)bK * N + nt * 128 + bN;
    const int tr = tid >> 4, tc = tid & 15;
    float acc[8][8];
#pragma unroll
    for (int i = 0; i < 8; i++)
#pragma unroll
        for (int j = 0; j < 8; j++) acc[i][j] = 0.f;
    float4 ra = *(const float4*)aPtr;
    float4 rb = *(const float4*)bPtr;
    for (int kt = 0; kt < K / 8; kt++) {
        As[aK][aRow] = ra.x; As[aK + 1][aRow] = ra.y; As[aK + 2][aRow] = ra.z; As[aK + 3][aRow] = ra.w;
        *(float4*)&Bs[bK][bN] = rb;
        __syncthreads();
        if (kt + 1 < K / 8) {
            ra = *(const float4*)(aPtr + (size_t)(kt + 1) * 8);
            rb = *(const float4*)(bPtr + (size_t)(kt + 1) * 8 * N);
        }
#pragma unroll
        for (int k = 0; k < 8; k++) {
            float4 a0 = *(const float4*)&As[k][tr * 8];
            float4 a1 = *(const float4*)&As[k][tr * 8 + 4];
            float4 b0 = *(const float4*)&Bs[k][tc * 8];
            float4 b1 = *(const float4*)&Bs[k][tc * 8 + 4];
            float ar[8] = {a0.x, a0.y, a0.z, a0.w, a1.x, a1.y, a1.z, a1.w};
            float br[8] = {b0.x, b0.y, b0.z, b0.w, b1.x, b1.y, b1.z, b1.w};
#pragma unroll
            for (int i = 0; i < 8; i++)
#pragma unroll
                for (int j = 0; j < 8; j++) acc[i][j] += ar[i] * br[j];
        }
        __syncthreads();
    }
#pragma unroll
    for (int i = 0; i < 8; i++) {
        float* cp = C + (size_t)(mt * 128 + tr * 8 + i) * N + nt * 128 + tc * 8;
#pragma unroll
        for (int j = 0; j < 8; j++) cp[j] = acc[i][j] + bias[nt * 128 + tc * 8 + j];
    }
}

// ---------------- HMMA grouped GEMM (fp16, fp32 acc, BKT=64, 8 warps 4x2, 3-stage single-sync) ----------------
// MODE 1: H = gelu(x[perm] @ W1t^T + b1) -> fp16   MODE 2: F = H @ W2t^T + b2 -> fp32
template <int MODE>
__global__ void __launch_bounds__(256)
moe_mma(const float* __restrict__ bias) {
    constexpr int K  = (MODE == 1) ? DDIM : HDIM;
    constexpr int NB = (MODE == 1) ? HDIM : DDIM;
    constexpr int NK = K / BKT;
    const int z = blockIdx.z, mt = blockIdx.y, nt = blockIdx.x;
    const int cnt = min(g_cursor[z], CAP);
    if (mt * BMT >= cnt) return;

    extern __shared__ __align__(128) char smem[];
    const unsigned sb = smem_u32(smem);
    const int tid = threadIdx.x, wid = tid >> 5, lane = tid & 31;

    // ---- load mapping: thread -> row tid>>2 (A: +0,64,128,192; B: +0,64), chunk pair (tid&3)*2 ----
    const int lrow = tid >> 2;
    const int chb = (tid & 3) * 2;
    size_t aOff[4];
#pragma unroll
    for (int i = 0; i < 4; i++) {
        int r = min(mt * BMT + lrow + 64 * i, cnt - 1);
        if (MODE == 1) aOff[i] = (size_t)g_perm[z * CAP + r] * DDIM;
        else           aOff[i] = ((size_t)z * CAP + r) * (size_t)HDIM;
    }
    const size_t bOff0 = ((size_t)z * NB + nt * BNT + lrow) * (size_t)K;
    const size_t bOff1 = ((size_t)z * NB + nt * BNT + lrow + 64) * (size_t)K;
    const __half* gA = (MODE == 1) ? g_xh : g_Hh;
    const __half* gB = (MODE == 1) ? g_w1t : g_w2t;

#define LOADC(cc, ss) do { \
        const unsigned st_ = sb + (ss) * STAGE; \
        const int ke_ = (cc) * BKT + chb * 8; \
        _Pragma("unroll") \
        for (int i = 0; i < 4; i++) { \
            CPA(st_ + swa(lrow + 64 * i, chb),     gA + aOff[i] + ke_); \
            CPA(st_ + swa(lrow + 64 * i, chb + 1), gA + aOff[i] + ke_ + 8); \
        } \
        CPA(st_ + OFF_B + swa(lrow, chb),          gB + bOff0 + ke_); \
        CPA(st_ + OFF_B + swa(lrow, chb + 1),      gB + bOff0 + ke_ + 8); \
        CPA(st_ + OFF_B + swa(lrow + 64, chb),     gB + bOff1 + ke_); \
        CPA(st_ + OFF_B + swa(lrow + 64, chb + 1), gB + bOff1 + ke_ + 8); \
        CPA_COMMIT(); \
    } while (0)

    // ---- compute mapping: 8 warps as 4(M) x 2(N); warp tile 64x64 ----
    const int m0 = (wid & 3) * 64;
    const int n0 = (wid >> 2) * 64;
    const int rA = ((lane >> 3) & 1) * 8 + (lane & 7);
    const int cA = lane >> 4;
    const int rB = (lane >> 4) * 8 + (lane & 7);
    const int cB = (lane >> 3) & 1;

    float acc[4][8][4];
#pragma unroll
    for (int f = 0; f < 4; f++)
#pragma unroll
        for (int g = 0; g < 8; g++)
#pragma unroll
            for (int q = 0; q < 4; q++) acc[f][g][q] = 0.f;

    LOADC(0, 0);
    LOADC(1, 1);
    int stg = 0;             // stage index of chunk c (c % 3)
    for (int c = 0; c < NK; c++) {
        if (c == NK - 1) CPA_WAIT0();
        else             CPA_WAIT1();         // chunk c landed
        __syncthreads();                      // all warps done with stage (c-1)%3
        if (c + 2 < NK) {
            int ws = stg + 2; if (ws >= NSTAGE) ws -= NSTAGE;
            LOADC(c + 2, ws);                 // overwrite stage (c-1)%3: safe
        }
        const unsigned st = sb + stg * STAGE;
#pragma unroll
        for (int kk = 0; kk < 4; kk++) {
            unsigned ah[4][4], bf[8][2];
#pragma unroll
            for (int f = 0; f < 4; f++)
                LDSM4(ah[f], st + swa(m0 + f * 16 + rA, kk * 2 + cA));
#pragma unroll
            for (int j = 0; j < 4; j++) {
                unsigned q[4];
                LDSM4(q, st + OFF_B + swa(n0 + j * 16 + rB, kk * 2 + cB));
                bf[2 * j][0] = q[0]; bf[2 * j][1] = q[1];
                bf[2 * j + 1][0] = q[2]; bf[2 * j + 1][1] = q[3];
            }
#pragma unroll
            for (int f = 0; f < 4; f++)
#pragma unroll
                for (int g = 0; g < 8; g++)
                    mma16816(acc[f][g], ah[f], bf[g]);
        }
        if (++stg == NSTAGE) stg = 0;
    }

    // ---- epilogue ----
    const float* bptr = bias + (size_t)z * NB + nt * BNT;
#pragma unroll
    for (int f = 0; f < 4; f++) {
#pragma unroll
        for (int h = 0; h < 2; h++) {
            const int mg = mt * BMT + m0 + f * 16 + (lane >> 2) + 8 * h;
            if (mg < cnt) {
                const size_t rowg = (size_t)z * CAP + mg;
#pragma unroll
                for (int g = 0; g < 8; g++) {
                    const int nc = n0 + g * 8 + (lane & 3) * 2;
                    float v0 = acc[f][g][2 * h + 0] + __ldg(bptr + nc);
                    float v1 = acc[f][g][2 * h + 1] + __ldg(bptr + nc + 1);
                    if (MODE == 1) {
                        v0 = 0.5f * v0 * (1.0f + erff(v0 * 0.70710678118654752f));
                        v1 = 0.5f * v1 * (1.0f + erff(v1 * 0.70710678118654752f));
                        __half2 hv = __floats2half2_rn(v0, v1);
                        *(unsigned*)(g_Hh + rowg * HDIM + nt * BNT + nc) = *(unsigned*)&hv;
                    } else {
                        *(float2*)(g_F + rowg * DDIM + nt * BNT + nc) = make_float2(v0, v1);
                    }
                }
            }
        }
    }
#undef LOADC
}

__global__ void final_kernel(const float* __restrict__ x, float* __restrict__ out) {
    int idx = blockIdx.x * blockDim.x + threadIdx.x;
    int n = idx >> 8, c = idx & 255;
    float4 xv = ((const float4*)x)[idx];
    int p0 = g_pos[n * 2], p1 = g_pos[n * 2 + 1];
    float gg0 = g_gate[n * 2], gg1 = g_gate[n * 2 + 1];
    const float4* F4 = (const float4*)g_F;
    float4 f0 = F4[(size_t)p0 * 256 + c];
    float4 f1 = F4[(size_t)p1 * 256 + c];
    ((float4*)out)[idx] = make_float4(xv.x + gg0 * f0.x + gg1 * f1.x,
                                      xv.y + gg0 * f0.y + gg1 * f1.y,
                                      xv.z + gg0 * f0.z + gg1 * f1.z,
                                      xv.w + gg0 * f0.w + gg1 * f1.w);
}

// ---------------- launch ----------------
extern "C" void kernel_launch(void* const* d_in, const int* in_sizes, int n_in,
                              void* d_out, int out_size) {
    const float* x    = (const float*)d_in[0];
    const float* Wp   = (const float*)d_in[1];
    const float* bp   = (const float*)d_in[2];
    const float* sim  = (const float*)d_in[3];
    const float* temp = (const float*)d_in[4];
    const float* W1   = (const float*)d_in[5];
    const float* b1   = (const float*)d_in[6];
    const float* W2   = (const float*)d_in[7];
    const float* b2   = (const float*)d_in[8];
    float* out = (float*)d_out;

    cudaFuncSetAttribute(moe_mma<1>, cudaFuncAttributeMaxDynamicSharedMemorySize, SMEM_DYN);
    cudaFuncSetAttribute(moe_mma<2>, cudaFuncAttributeMaxDynamicSharedMemorySize, SMEM_DYN);

    // device addresses for any symbol passed as a HOST-side kernel argument
    void *pP = nullptr, *pw1 = nullptr, *pw2 = nullptr;
    cudaGetSymbolAddress(&pP, g_P);
    cudaGetSymbolAddress(&pw1, g_w1t);
    cudaGetSymbolAddress(&pw2, g_w2t);

    init_kernel<<<1, 32>>>();
    simn_kernel<<<1, 32>>>(sim);
    gemm_p<<<dim3(PROJD / 128, NTOK / 128), 256>>>(x, Wp, bp, (float*)pP);
    gating_kernel<<<(NTOK * 32) / 256, 256>>>((const float*)pP, temp);

    conv_x_kernel<<<(NTOK * DDIM / 4) / 256, 256>>>(x, NTOK * DDIM / 4);
    conv_wt_kernel<<<dim3(HDIM / 32, DDIM / 32, NEXP), dim3(32, 8)>>>(W1, (__half*)pw1, DDIM, HDIM);
    conv_wt_kernel<<<dim3(DDIM / 32, HDIM / 32, NEXP), dim3(32, 8)>>>(W2, (__half*)pw2, HDIM, DDIM);

    moe_mma<1><<<dim3(HDIM / BNT, CAP / BMT, NEXP), 256, SMEM_DYN>>>(b1);
    moe_mma<2><<<dim3(DDIM / BNT, CAP / BMT, NEXP), 256, SMEM_DYN>>>(b2);

    final_kernel<<<(NTOK * DDIM / 4) / 256, 256>>>(x, out);
}

// round 16
// speedup vs baseline: 1.1258x; 1.0016x over previous
#include <cuda_runtime.h>
#include <cuda_fp16.h>
#include <math.h>

#define NTOK 16384
#define DDIM 1024
#define HDIM 4096
#define NEXP 8
#define PROJD 256
#define CAP 12288
#define CLAMP_MAXV 4.605170185988091f

#define BMT 256
#define BNT 128
#define BKT 64
#define A_BYTES 32768
#define B_BYTES 16384
#define OFF_B A_BYTES
#define STAGE (A_BYTES + B_BYTES)
#define NSTAGE 3
#define SMEM_DYN (NSTAGE * STAGE)

// ---------------- device scratch ----------------
__device__ float g_P[NTOK * PROJD];
__device__ float g_simn[PROJD * NEXP];
__device__ int   g_perm[NEXP * CAP];
__device__ float g_gateP[NEXP * CAP];
__device__ int   g_cursor[NEXP];
__device__ __half g_xh[(size_t)NTOK * DDIM];
__device__ __half g_w1t[(size_t)NEXP * HDIM * DDIM];
__device__ __half g_w2t[(size_t)NEXP * DDIM * HDIM];
__device__ __half g_Hh[(size_t)NEXP * CAP * HDIM];

// ---------------- helpers ----------------
__device__ __forceinline__ unsigned smem_u32(const void* p) {
    unsigned a;
    asm("{ .reg .u64 t; cvta.to.shared.u64 t, %1; cvt.u32.u64 %0, t; }" : "=r"(a) : "l"(p));
    return a;
}
#define CPA(dst, src) asm volatile("cp.async.cg.shared.global [%0], [%1], 16;" :: "r"(dst), "l"(src))
#define CPA_COMMIT()  asm volatile("cp.async.commit_group;" ::: "memory")
#define CPA_WAIT1()   asm volatile("cp.async.wait_group 1;" ::: "memory")
#define CPA_WAIT0()   asm volatile("cp.async.wait_group 0;" ::: "memory")
#define LDSM4(R, A) asm volatile("ldmatrix.sync.aligned.m8n8.x4.shared.b16 {%0,%1,%2,%3}, [%4];" \
    : "=r"((R)[0]), "=r"((R)[1]), "=r"((R)[2]), "=r"((R)[3]) : "r"(A))
#define FMA2(d, a, b) asm("fma.rn.f32x2 %0, %1, %2, %0;" : "+l"(d) : "l"(a), "l"(b))
#define PACKDUP(d, s) asm("mov.b64 %0, {%1, %1};" : "=l"(d) : "f"(s))
#define UNPACK2(lo, hi, in) asm("mov.b64 {%0, %1}, %2;" : "=f"(lo), "=f"(hi) : "l"(in))

__device__ __forceinline__ void mma16816(float* c, const unsigned* a, const unsigned* b) {
    asm volatile(
        "mma.sync.aligned.m16n8k16.row.col.f32.f16.f16.f32 "
        "{%0,%1,%2,%3}, {%4,%5,%6,%7}, {%8,%9}, {%0,%1,%2,%3};"
        : "+f"(c[0]), "+f"(c[1]), "+f"(c[2]), "+f"(c[3])
        : "r"(a[0]), "r"(a[1]), "r"(a[2]), "r"(a[3]), "r"(b[0]), "r"(b[1]));
}
__device__ __forceinline__ unsigned swa(int r, int ch) {
    return (unsigned)(r * 128 + ((ch ^ (r & 7)) << 4));
}

// ---------------- small kernels ----------------
__global__ void init_kernel() { if (threadIdx.x < NEXP) g_cursor[threadIdx.x] = 0; }

__global__ void simn_kernel(const float* __restrict__ sim) {
    int e = threadIdx.x;
    if (e < NEXP) {
        float s = 0.f;
        for (int j = 0; j < PROJD; j++) { float v = sim[j * NEXP + e]; s += v * v; }
        float inv = 1.f / fmaxf(sqrtf(s), 1e-12f);
        for (int j = 0; j < PROJD; j++) g_simn[j * NEXP + e] = sim[j * NEXP + e] * inv;
    }
}

__global__ void gating_kernel(const float* __restrict__ P, const float* __restrict__ temp) {
    __shared__ float ssim[PROJD * NEXP];
    for (int i = threadIdx.x; i < PROJD * NEXP; i += blockDim.x) ssim[i] = g_simn[i];
    __syncthreads();
    int tok = (blockIdx.x * blockDim.x + threadIdx.x) >> 5;
    int lane = threadIdx.x & 31;
    if (tok >= NTOK) return;
    const float* row = P + (size_t)tok * PROJD;
    float dot[NEXP];
#pragma unroll
    for (int e = 0; e < NEXP; e++) dot[e] = 0.f;
    float ss = 0.f;
#pragma unroll
    for (int i = 0; i < PROJD / 32; i++) {
        float p = row[lane + 32 * i];
        ss += p * p;
        const float* sr = ssim + (lane + 32 * i) * NEXP;
#pragma unroll
        for (int e = 0; e < NEXP; e++) dot[e] += p * sr[e];
    }
#pragma unroll
    for (int off = 16; off; off >>= 1) {
        ss += __shfl_down_sync(0xffffffffu, ss, off);
#pragma unroll
        for (int e = 0; e < NEXP; e++) dot[e] += __shfl_down_sync(0xffffffffu, dot[e], off);
    }
    if (lane == 0) {
        float scale = expf(fminf(temp[0], CLAMP_MAXV));
        float inv = 1.f / fmaxf(sqrtf(ss), 1e-12f);
        float lg[NEXP];
#pragma unroll
        for (int e = 0; e < NEXP; e++) lg[e] = dot[e] * inv * scale;
        int e0 = 0;
#pragma unroll
        for (int e = 1; e < NEXP; e++) if (lg[e] > lg[e0]) e0 = e;
        int e1 = (e0 == 0) ? 1 : 0;
#pragma unroll
        for (int e = 0; e < NEXP; e++) if (e != e0 && lg[e] > lg[e1]) e1 = e;
        float ex = expf(lg[e1] - lg[e0]);
        float den = 1.f + ex;
        int p0 = atomicAdd(&g_cursor[e0], 1); p0 = min(p0, CAP - 1);
        g_perm[e0 * CAP + p0] = tok;
        g_gateP[e0 * CAP + p0] = 1.f / den;
        int p1 = atomicAdd(&g_cursor[e1], 1); p1 = min(p1, CAP - 1);
        g_perm[e1 * CAP + p1] = tok;
        g_gateP[e1 * CAP + p1] = ex / den;
    }
}

__global__ void conv_x_kernel(const float* __restrict__ src, int n4) {
    int i = blockIdx.x * blockDim.x + threadIdx.x;
    if (i >= n4) return;
    float4 v = ((const float4*)src)[i];
    __half2 a = __floats2half2_rn(v.x, v.y);
    __half2 b = __floats2half2_rn(v.z, v.w);
    ((uint2*)g_xh)[i] = make_uint2(*(unsigned*)&a, *(unsigned*)&b);
}

// out = x  (re-initialized every replay; moe_mma<2> accumulates into it)
__global__ void copy_out_kernel(const float* __restrict__ x, float* __restrict__ out) {
    int i = blockIdx.x * blockDim.x + threadIdx.x;
    ((float4*)out)[i] = ((const float4*)x)[i];
}

// W [E][R][C] fp32 -> T [E][C][R] fp16  (T must be a cudaGetSymbolAddress pointer!)
__global__ void conv_wt_kernel(const float* __restrict__ W, __half* __restrict__ T, int R, int C) {
    __shared__ float tile[32][33];
    int e = blockIdx.z, r0 = blockIdx.y * 32, c0 = blockIdx.x * 32;
    const float* Wp = W + (size_t)e * R * C;
    for (int i = threadIdx.y; i < 32; i += 8)
        tile[i][threadIdx.x] = Wp[(size_t)(r0 + i) * C + c0 + threadIdx.x];
    __syncthreads();
    for (int i = threadIdx.y; i < 32; i += 8)
        T[((size_t)e * C + c0 + i) * R + r0 + threadIdx.x] = __float2half_rn(tile[threadIdx.x][i]);
}

// fp32 SGEMM for gating projection; FFMA2 (f32x2) inner kernel.
// Per-lane scalar math identical to plain FFMA -> bit-identical logits.
__global__ __launch_bounds__(256, 2)
void gemm_p(const float* __restrict__ A, const float* __restrict__ Bw,
            const float* __restrict__ bias, float* __restrict__ C) {
    const int K = DDIM, N = PROJD;
    const int mt = blockIdx.y, nt = blockIdx.x;
    __shared__ __align__(16) float As[8][128], Bs[8][128];
    const int tid = threadIdx.x;
    const int aRow = tid >> 1, aK = (tid & 1) * 4;
    const int bK = tid >> 5, bN = (tid & 31) * 4;
    const float* aPtr = A + (size_t)(mt * 128 + aRow) * K + aK;
    const float* bPtr = Bw + (size_t)bK * N + nt * 128 + bN;
    const int tr = tid >> 4, tc = tid & 15;
    unsigned long long acc2[4][8];   // [row-pair][col] : rows (tr*8+2i, tr*8+2i+1)
#pragma unroll
    for (int i = 0; i < 4; i++)
#pragma unroll
        for (int j = 0; j < 8; j++) acc2[i][j] = 0ULL;
    float4 ra = *(const float4*)aPtr;
    float4 rb = *(const float4*)bPtr;
    for (int kt = 0; kt < K / 8; kt++) {
        As[aK][aRow] = ra.x; As[aK + 1][aRow] = ra.y; As[aK + 2][aRow] = ra.z; As[aK + 3][aRow] = ra.w;
        *(float4*)&Bs[bK][bN] = rb;
        __syncthreads();
        if (kt + 1 < K / 8) {
            ra = *(const float4*)(aPtr + (size_t)(kt + 1) * 8);
            rb = *(const float4*)(bPtr + (size_t)(kt + 1) * 8 * N);
        }
#pragma unroll
        for (int k = 0; k < 8; k++) {
            // A row-pairs load directly as 8B; As row base is 16B aligned, tr*8*4+2i*4 -> 8B aligned
            unsigned long long aa[4];
#pragma unroll
            for (int i = 0; i < 4; i++)
                aa[i] = *(const unsigned long long*)&As[k][tr * 8 + 2 * i];
            float4 b0 = *(const float4*)&Bs[k][tc * 8];
            float4 b1 = *(const float4*)&Bs[k][tc * 8 + 4];
            float br[8] = {b0.x, b0.y, b0.z, b0.w, b1.x, b1.y, b1.z, b1.w};
            unsigned long long bb[8];
#pragma unroll
            for (int j = 0; j < 8; j++) PACKDUP(bb[j], br[j]);
#pragma unroll
            for (int i = 0; i < 4; i++)
#pragma unroll
                for (int j = 0; j < 8; j++) FMA2(acc2[i][j], aa[i], bb[j]);
        }
        __syncthreads();
    }
#pragma unroll
    for (int i = 0; i < 4; i++) {
        float* cp0 = C + (size_t)(mt * 128 + tr * 8 + 2 * i) * N + nt * 128 + tc * 8;
        float* cp1 = cp0 + N;
#pragma unroll
        for (int j = 0; j < 8; j++) {
            float v0, v1;
            UNPACK2(v0, v1, acc2[i][j]);
            float bv = bias[nt * 128 + tc * 8 + j];
            cp0[j] = v0 + bv;
            cp1[j] = v1 + bv;
        }
    }
}

// ---------------- HMMA grouped GEMM (fp16, fp32 acc, BKT=64, 8 warps 4x2, 3-stage single-sync) ----------------
// MODE 1: H = gelu(x[perm] @ W1t^T + b1) -> fp16
// MODE 2: out[tok] += gate * (H @ W2t^T + b2)   (atomic accumulate; out pre-set to x)
template <int MODE>
__global__ void __launch_bounds__(256)
moe_mma(const float* __restrict__ bias, float* __restrict__ outp) {
    constexpr int K  = (MODE == 1) ? DDIM : HDIM;
    constexpr int NB = (MODE == 1) ? HDIM : DDIM;
    constexpr int NK = K / BKT;
    const int z = blockIdx.z, mt = blockIdx.y, nt = blockIdx.x;
    const int cnt = min(g_cursor[z], CAP);
    if (mt * BMT >= cnt) return;

    extern __shared__ __align__(128) char smem[];
    const unsigned sb = smem_u32(smem);
    const int tid = threadIdx.x, wid = tid >> 5, lane = tid & 31;

    const int lrow = tid >> 2;
    const int chb = (tid & 3) * 2;
    size_t aOff[4];
#pragma unroll
    for (int i = 0; i < 4; i++) {
        int r = min(mt * BMT + lrow + 64 * i, cnt - 1);
        if (MODE == 1) aOff[i] = (size_t)g_perm[z * CAP + r] * DDIM;
        else           aOff[i] = ((size_t)z * CAP + r) * (size_t)HDIM;
    }
    const size_t bOff0 = ((size_t)z * NB + nt * BNT + lrow) * (size_t)K;
    const size_t bOff1 = ((size_t)z * NB + nt * BNT + lrow + 64) * (size_t)K;
    const __half* gA = (MODE == 1) ? g_xh : g_Hh;
    const __half* gB = (MODE == 1) ? g_w1t : g_w2t;

#define LOADC(cc, ss) do { \
        const unsigned st_ = sb + (ss) * STAGE; \
        const int ke_ = (cc) * BKT + chb * 8; \
        _Pragma("unroll") \
        for (int i = 0; i < 4; i++) { \
            CPA(st_ + swa(lrow + 64 * i, chb),     gA + aOff[i] + ke_); \
            CPA(st_ + swa(lrow + 64 * i, chb + 1), gA + aOff[i] + ke_ + 8); \
        } \
        CPA(st_ + OFF_B + swa(lrow, chb),          gB + bOff0 + ke_); \
        CPA(st_ + OFF_B + swa(lrow, chb + 1),      gB + bOff0 + ke_ + 8); \
        CPA(st_ + OFF_B + swa(lrow + 64, chb),     gB + bOff1 + ke_); \
        CPA(st_ + OFF_B + swa(lrow + 64, chb + 1), gB + bOff1 + ke_ + 8); \
        CPA_COMMIT(); \
    } while (0)

    const int m0 = (wid & 3) * 64;
    const int n0 = (wid >> 2) * 64;
    const int rA = ((lane >> 3) & 1) * 8 + (lane & 7);
    const int cA = lane >> 4;
    const int rB = (lane >> 4) * 8 + (lane & 7);
    const int cB = (lane >> 3) & 1;

    float acc[4][8][4];
#pragma unroll
    for (int f = 0; f < 4; f++)
#pragma unroll
        for (int g = 0; g < 8; g++)
#pragma unroll
            for (int q = 0; q < 4; q++) acc[f][g][q] = 0.f;

    LOADC(0, 0);
    LOADC(1, 1);
    int stg = 0;
    for (int c = 0; c < NK; c++) {
        if (c == NK - 1) CPA_WAIT0();
        else             CPA_WAIT1();
        __syncthreads();
        if (c + 2 < NK) {
            int ws = stg + 2; if (ws >= NSTAGE) ws -= NSTAGE;
            LOADC(c + 2, ws);
        }
        const unsigned st = sb + stg * STAGE;
#pragma unroll
        for (int kk = 0; kk < 4; kk++) {
            unsigned ah[4][4], bf[8][2];
#pragma unroll
            for (int f = 0; f < 4; f++)
                LDSM4(ah[f], st + swa(m0 + f * 16 + rA, kk * 2 + cA));
#pragma unroll
            for (int j = 0; j < 4; j++) {
                unsigned q[4];
                LDSM4(q, st + OFF_B + swa(n0 + j * 16 + rB, kk * 2 + cB));
                bf[2 * j][0] = q[0]; bf[2 * j][1] = q[1];
                bf[2 * j + 1][0] = q[2]; bf[2 * j + 1][1] = q[3];
            }
#pragma unroll
            for (int f = 0; f < 4; f++)
#pragma unroll
                for (int g = 0; g < 8; g++)
                    mma16816(acc[f][g], ah[f], bf[g]);
        }
        if (++stg == NSTAGE) stg = 0;
    }

    const float* bptr = bias + (size_t)z * NB + nt * BNT;
#pragma unroll
    for (int f = 0; f < 4; f++) {
#pragma unroll
        for (int h = 0; h < 2; h++) {
            const int mg = mt * BMT + m0 + f * 16 + (lane >> 2) + 8 * h;
            if (mg < cnt) {
                if (MODE == 1) {
                    const size_t rowg = (size_t)z * CAP + mg;
#pragma unroll
                    for (int g = 0; g < 8; g++) {
                        const int nc = n0 + g * 8 + (lane & 3) * 2;
                        float v0 = acc[f][g][2 * h + 0] + __ldg(bptr + nc);
                        float v1 = acc[f][g][2 * h + 1] + __ldg(bptr + nc + 1);
                        v0 = 0.5f * v0 * (1.0f + erff(v0 * 0.70710678118654752f));
                        v1 = 0.5f * v1 * (1.0f + erff(v1 * 0.70710678118654752f));
                        __half2 hv = __floats2half2_rn(v0, v1);
                        *(unsigned*)(g_Hh + rowg * HDIM + nt * BNT + nc) = *(unsigned*)&hv;
                    }
                } else {
                    const int tok = g_perm[z * CAP + mg];
                    const float gate = g_gateP[z * CAP + mg];
                    float* op = outp + (size_t)tok * DDIM + nt * BNT;
#pragma unroll
                    for (int g = 0; g < 8; g++) {
                        const int nc = n0 + g * 8 + (lane & 3) * 2;
                        float v0 = acc[f][g][2 * h + 0] + __ldg(bptr + nc);
                        float v1 = acc[f][g][2 * h + 1] + __ldg(bptr + nc + 1);
                        atomicAdd(op + nc,     gate * v0);
                        atomicAdd(op + nc + 1, gate * v1);
                    }
                }
            }
        }
    }
#undef LOADC
}

// ---------------- launch (serial; no streams) ----------------
extern "C" void kernel_launch(void* const* d_in, const int* in_sizes, int n_in,
                              void* d_out, int out_size) {
    const float* x    = (const float*)d_in[0];
    const float* Wp   = (const float*)d_in[1];
    const float* bp   = (const float*)d_in[2];
    const float* sim  = (const float*)d_in[3];
    const float* temp = (const float*)d_in[4];
    const float* W1   = (const float*)d_in[5];
    const float* b1   = (const float*)d_in[6];
    const float* W2   = (const float*)d_in[7];
    const float* b2   = (const float*)d_in[8];
    float* out = (float*)d_out;

    cudaFuncSetAttribute(moe_mma<1>, cudaFuncAttributeMaxDynamicSharedMemorySize, SMEM_DYN);
    cudaFuncSetAttribute(moe_mma<2>, cudaFuncAttributeMaxDynamicSharedMemorySize, SMEM_DYN);

    void *pP = nullptr, *pw1 = nullptr, *pw2 = nullptr;
    cudaGetSymbolAddress(&pP, g_P);
    cudaGetSymbolAddress(&pw1, g_w1t);
    cudaGetSymbolAddress(&pw2, g_w2t);

    init_kernel<<<1, 32>>>();
    simn_kernel<<<1, 32>>>(sim);
    gemm_p<<<dim3(PROJD / 128, NTOK / 128), 256>>>(x, Wp, bp, (float*)pP);
    gating_kernel<<<(NTOK * 32) / 256, 256>>>((const float*)pP, temp);

    conv_x_kernel<<<(NTOK * DDIM / 4) / 256, 256>>>(x, NTOK * DDIM / 4);
    conv_wt_kernel<<<dim3(HDIM / 32, DDIM / 32, NEXP), dim3(32, 8)>>>(W1, (__half*)pw1, DDIM, HDIM);
    conv_wt_kernel<<<dim3(DDIM / 32, HDIM / 32, NEXP), dim3(32, 8)>>>(W2, (__half*)pw2, HDIM, DDIM);
    copy_out_kernel<<<(NTOK * DDIM / 4) / 256, 256>>>(x, out);

    moe_mma<1><<<dim3(HDIM / BNT, CAP / BMT, NEXP), 256, SMEM_DYN>>>(b1, nullptr);
    moe_mma<2><<<dim3(DDIM / BNT, CAP / BMT, NEXP), 256, SMEM_DYN>>>(b2, out);
}

// round 17
// speedup vs baseline: 1.1264x; 1.0005x over previous
#include <cuda_runtime.h>
#include <cuda_fp16.h>
#include <math.h>

#define NTOK 16384
#define DDIM 1024
#define HDIM 4096
#define NEXP 8
#define PROJD 256
#define CAP 12288
#define CLAMP_MAXV 4.605170185988091f

#define BMT 256
#define BNT 128
#define BKT 64
#define A_BYTES 32768
#define B_BYTES 16384
#define OFF_B A_BYTES
#define STAGE (A_BYTES + B_BYTES)
#define NSTAGE 3
#define SMEM_DYN (NSTAGE * STAGE)
#define PBK 16

// ---------------- device scratch ----------------
__device__ float g_P[NTOK * PROJD];
__device__ float g_simn[PROJD * NEXP];
__device__ int   g_perm[NEXP * CAP];
__device__ float g_gateP[NEXP * CAP];
__device__ int   g_cursor[NEXP];
__device__ __half g_xh[(size_t)NTOK * DDIM];
__device__ __half g_w1t[(size_t)NEXP * HDIM * DDIM];
__device__ __half g_w2t[(size_t)NEXP * DDIM * HDIM];
__device__ __half g_Hh[(size_t)NEXP * CAP * HDIM];

// ---------------- helpers ----------------
__device__ __forceinline__ unsigned smem_u32(const void* p) {
    unsigned a;
    asm("{ .reg .u64 t; cvta.to.shared.u64 t, %1; cvt.u32.u64 %0, t; }" : "=r"(a) : "l"(p));
    return a;
}
#define CPA(dst, src) asm volatile("cp.async.cg.shared.global [%0], [%1], 16;" :: "r"(dst), "l"(src))
#define CPA_COMMIT()  asm volatile("cp.async.commit_group;" ::: "memory")
#define CPA_WAIT1()   asm volatile("cp.async.wait_group 1;" ::: "memory")
#define CPA_WAIT0()   asm volatile("cp.async.wait_group 0;" ::: "memory")
#define LDSM4(R, A) asm volatile("ldmatrix.sync.aligned.m8n8.x4.shared.b16 {%0,%1,%2,%3}, [%4];" \
    : "=r"((R)[0]), "=r"((R)[1]), "=r"((R)[2]), "=r"((R)[3]) : "r"(A))
#define FMA2(d, a, b) asm("fma.rn.f32x2 %0, %1, %2, %0;" : "+l"(d) : "l"(a), "l"(b))
#define PACKDUP(d, s) asm("mov.b64 %0, {%1, %1};" : "=l"(d) : "f"(s))
#define UNPACK2(lo, hi, in) asm("mov.b64 {%0, %1}, %2;" : "=f"(lo), "=f"(hi) : "l"(in))

__device__ __forceinline__ void mma16816(float* c, const unsigned* a, const unsigned* b) {
    asm volatile(
        "mma.sync.aligned.m16n8k16.row.col.f32.f16.f16.f32 "
        "{%0,%1,%2,%3}, {%4,%5,%6,%7}, {%8,%9}, {%0,%1,%2,%3};"
        : "+f"(c[0]), "+f"(c[1]), "+f"(c[2]), "+f"(c[3])
        : "r"(a[0]), "r"(a[1]), "r"(a[2]), "r"(a[3]), "r"(b[0]), "r"(b[1]));
}
__device__ __forceinline__ unsigned swa(int r, int ch) {
    return (unsigned)(r * 128 + ((ch ^ (r & 7)) << 4));
}

// ---------------- small kernels ----------------
__global__ void init_kernel() { if (threadIdx.x < NEXP) g_cursor[threadIdx.x] = 0; }

__global__ void simn_kernel(const float* __restrict__ sim) {
    int e = threadIdx.x;
    if (e < NEXP) {
        float s = 0.f;
        for (int j = 0; j < PROJD; j++) { float v = sim[j * NEXP + e]; s += v * v; }
        float inv = 1.f / fmaxf(sqrtf(s), 1e-12f);
        for (int j = 0; j < PROJD; j++) g_simn[j * NEXP + e] = sim[j * NEXP + e] * inv;
    }
}

__global__ void gating_kernel(const float* __restrict__ P, const float* __restrict__ temp) {
    __shared__ float ssim[PROJD * NEXP];
    for (int i = threadIdx.x; i < PROJD * NEXP; i += blockDim.x) ssim[i] = g_simn[i];
    __syncthreads();
    int tok = (blockIdx.x * blockDim.x + threadIdx.x) >> 5;
    int lane = threadIdx.x & 31;
    if (tok >= NTOK) return;
    const float* row = P + (size_t)tok * PROJD;
    float dot[NEXP];
#pragma unroll
    for (int e = 0; e < NEXP; e++) dot[e] = 0.f;
    float ss = 0.f;
#pragma unroll
    for (int i = 0; i < PROJD / 32; i++) {
        float p = row[lane + 32 * i];
        ss += p * p;
        const float* sr = ssim + (lane + 32 * i) * NEXP;
#pragma unroll
        for (int e = 0; e < NEXP; e++) dot[e] += p * sr[e];
    }
#pragma unroll
    for (int off = 16; off; off >>= 1) {
        ss += __shfl_down_sync(0xffffffffu, ss, off);
#pragma unroll
        for (int e = 0; e < NEXP; e++) dot[e] += __shfl_down_sync(0xffffffffu, dot[e], off);
    }
    if (lane == 0) {
        float scale = expf(fminf(temp[0], CLAMP_MAXV));
        float inv = 1.f / fmaxf(sqrtf(ss), 1e-12f);
        float lg[NEXP];
#pragma unroll
        for (int e = 0; e < NEXP; e++) lg[e] = dot[e] * inv * scale;
        int e0 = 0;
#pragma unroll
        for (int e = 1; e < NEXP; e++) if (lg[e] > lg[e0]) e0 = e;
        int e1 = (e0 == 0) ? 1 : 0;
#pragma unroll
        for (int e = 0; e < NEXP; e++) if (e != e0 && lg[e] > lg[e1]) e1 = e;
        float ex = expf(lg[e1] - lg[e0]);
        float den = 1.f + ex;
        int p0 = atomicAdd(&g_cursor[e0], 1); p0 = min(p0, CAP - 1);
        g_perm[e0 * CAP + p0] = tok;
        g_gateP[e0 * CAP + p0] = 1.f / den;
        int p1 = atomicAdd(&g_cursor[e1], 1); p1 = min(p1, CAP - 1);
        g_perm[e1 * CAP + p1] = tok;
        g_gateP[e1 * CAP + p1] = ex / den;
    }
}

__global__ void conv_x_kernel(const float* __restrict__ src, int n4) {
    int i = blockIdx.x * blockDim.x + threadIdx.x;
    if (i >= n4) return;
    float4 v = ((const float4*)src)[i];
    __half2 a = __floats2half2_rn(v.x, v.y);
    __half2 b = __floats2half2_rn(v.z, v.w);
    ((uint2*)g_xh)[i] = make_uint2(*(unsigned*)&a, *(unsigned*)&b);
}

// out = x  (re-initialized every replay; moe_mma<2> accumulates into it)
__global__ void copy_out_kernel(const float* __restrict__ x, float* __restrict__ out) {
    int i = blockIdx.x * blockDim.x + threadIdx.x;
    ((float4*)out)[i] = ((const float4*)x)[i];
}

// W [E][R][C] fp32 -> T [E][C][R] fp16  (T must be a cudaGetSymbolAddress pointer!)
__global__ void conv_wt_kernel(const float* __restrict__ W, __half* __restrict__ T, int R, int C) {
    __shared__ float tile[32][33];
    int e = blockIdx.z, r0 = blockIdx.y * 32, c0 = blockIdx.x * 32;
    const float* Wp = W + (size_t)e * R * C;
    for (int i = threadIdx.y; i < 32; i += 8)
        tile[i][threadIdx.x] = Wp[(size_t)(r0 + i) * C + c0 + threadIdx.x];
    __syncthreads();
    for (int i = threadIdx.y; i < 32; i += 8)
        T[((size_t)e * C + c0 + i) * R + r0 + threadIdx.x] = __float2half_rn(tile[threadIdx.x][i]);
}

// fp32 SGEMM for gating projection; FFMA2 inner kernel, BK=16,
// register-prefetch double buffer, ONE __syncthreads per K-iteration.
// Per-lane scalar math identical to R16 -> bit-identical logits.
__global__ __launch_bounds__(256, 2)
void gemm_p(const float* __restrict__ A, const float* __restrict__ Bw,
            const float* __restrict__ bias, float* __restrict__ C) {
    const int K = DDIM, N = PROJD;
    const int mt = blockIdx.y, nt = blockIdx.x;
    __shared__ __align__(16) float As[2][PBK][128], Bs[2][PBK][128];
    const int tid = threadIdx.x;
    // A: thread -> row tid>>1, k-base (tid&1)*8  (8 floats)
    const int aRow = tid >> 1, aK = (tid & 1) * 8;
    // B: thread -> k-row tid>>4, col-base (tid&15)*8  (8 floats)
    const int bK = tid >> 4, bN = (tid & 15) * 8;
    const float* aPtr = A + (size_t)(mt * 128 + aRow) * K + aK;
    const float* bPtr = Bw + (size_t)bK * N + nt * 128 + bN;
    const int tr = tid >> 4, tc = tid & 15;

    unsigned long long acc2[4][8];
#pragma unroll
    for (int i = 0; i < 4; i++)
#pragma unroll
        for (int j = 0; j < 8; j++) acc2[i][j] = 0ULL;

    float4 ra0 = *(const float4*)aPtr;
    float4 ra1 = *(const float4*)(aPtr + 4);
    float4 rb0 = *(const float4*)bPtr;
    float4 rb1 = *(const float4*)(bPtr + 4);

    // store chunk 0 into stage 0
    As[0][aK + 0][aRow] = ra0.x; As[0][aK + 1][aRow] = ra0.y;
    As[0][aK + 2][aRow] = ra0.z; As[0][aK + 3][aRow] = ra0.w;
    As[0][aK + 4][aRow] = ra1.x; As[0][aK + 5][aRow] = ra1.y;
    As[0][aK + 6][aRow] = ra1.z; As[0][aK + 7][aRow] = ra1.w;
    *(float4*)&Bs[0][bK][bN] = rb0;
    *(float4*)&Bs[0][bK][bN + 4] = rb1;
    __syncthreads();

    const int NKP = K / PBK;
    for (int c = 0; c < NKP; c++) {
        const int s = c & 1;
        if (c + 1 < NKP) {
            ra0 = *(const float4*)(aPtr + (size_t)(c + 1) * PBK);
            ra1 = *(const float4*)(aPtr + (size_t)(c + 1) * PBK + 4);
            rb0 = *(const float4*)(bPtr + (size_t)(c + 1) * PBK * N);
            rb1 = *(const float4*)(bPtr + (size_t)(c + 1) * PBK * N + 4);
        }
#pragma unroll
        for (int k = 0; k < PBK; k++) {
            unsigned long long aa[4];
#pragma unroll
            for (int i = 0; i < 4; i++)
                aa[i] = *(const unsigned long long*)&As[s][k][tr * 8 + 2 * i];
            float4 b0 = *(const float4*)&Bs[s][k][tc * 8];
            float4 b1 = *(const float4*)&Bs[s][k][tc * 8 + 4];
            float br[8] = {b0.x, b0.y, b0.z, b0.w, b1.x, b1.y, b1.z, b1.w};
            unsigned long long bb[8];
#pragma unroll
            for (int j = 0; j < 8; j++) PACKDUP(bb[j], br[j]);
#pragma unroll
            for (int i = 0; i < 4; i++)
#pragma unroll
                for (int j = 0; j < 8; j++) FMA2(acc2[i][j], aa[i], bb[j]);
        }
        if (c + 1 < NKP) {
            const int d = s ^ 1;
            As[d][aK + 0][aRow] = ra0.x; As[d][aK + 1][aRow] = ra0.y;
            As[d][aK + 2][aRow] = ra0.z; As[d][aK + 3][aRow] = ra0.w;
            As[d][aK + 4][aRow] = ra1.x; As[d][aK + 5][aRow] = ra1.y;
            As[d][aK + 6][aRow] = ra1.z; As[d][aK + 7][aRow] = ra1.w;
            *(float4*)&Bs[d][bK][bN] = rb0;
            *(float4*)&Bs[d][bK][bN + 4] = rb1;
        }
        __syncthreads();
    }

#pragma unroll
    for (int i = 0; i < 4; i++) {
        float* cp0 = C + (size_t)(mt * 128 + tr * 8 + 2 * i) * N + nt * 128 + tc * 8;
        float* cp1 = cp0 + N;
#pragma unroll
        for (int j = 0; j < 8; j++) {
            float v0, v1;
            UNPACK2(v0, v1, acc2[i][j]);
            float bv = bias[nt * 128 + tc * 8 + j];
            cp0[j] = v0 + bv;
            cp1[j] = v1 + bv;
        }
    }
}

// ---------------- HMMA grouped GEMM (fp16, fp32 acc, BKT=64, 8 warps 4x2, 3-stage single-sync) ----------------
// MODE 1: H = gelu(x[perm] @ W1t^T + b1) -> fp16
// MODE 2: out[tok] += gate * (H @ W2t^T + b2)   (atomic accumulate; out pre-set to x)
template <int MODE>
__global__ void __launch_bounds__(256)
moe_mma(const float* __restrict__ bias, float* __restrict__ outp) {
    constexpr int K  = (MODE == 1) ? DDIM : HDIM;
    constexpr int NB = (MODE == 1) ? HDIM : DDIM;
    constexpr int NK = K / BKT;
    const int z = blockIdx.z, mt = blockIdx.y, nt = blockIdx.x;
    const int cnt = min(g_cursor[z], CAP);
    if (mt * BMT >= cnt) return;

    extern __shared__ __align__(128) char smem[];
    const unsigned sb = smem_u32(smem);
    const int tid = threadIdx.x, wid = tid >> 5, lane = tid & 31;

    const int lrow = tid >> 2;
    const int chb = (tid & 3) * 2;
    size_t aOff[4];
#pragma unroll
    for (int i = 0; i < 4; i++) {
        int r = min(mt * BMT + lrow + 64 * i, cnt - 1);
        if (MODE == 1) aOff[i] = (size_t)g_perm[z * CAP + r] * DDIM;
        else           aOff[i] = ((size_t)z * CAP + r) * (size_t)HDIM;
    }
    const size_t bOff0 = ((size_t)z * NB + nt * BNT + lrow) * (size_t)K;
    const size_t bOff1 = ((size_t)z * NB + nt * BNT + lrow + 64) * (size_t)K;
    const __half* gA = (MODE == 1) ? g_xh : g_Hh;
    const __half* gB = (MODE == 1) ? g_w1t : g_w2t;

#define LOADC(cc, ss) do { \
        const unsigned st_ = sb + (ss) * STAGE; \
        const int ke_ = (cc) * BKT + chb * 8; \
        _Pragma("unroll") \
        for (int i = 0; i < 4; i++) { \
            CPA(st_ + swa(lrow + 64 * i, chb),     gA + aOff[i] + ke_); \
            CPA(st_ + swa(lrow + 64 * i, chb + 1), gA + aOff[i] + ke_ + 8); \
        } \
        CPA(st_ + OFF_B + swa(lrow, chb),          gB + bOff0 + ke_); \
        CPA(st_ + OFF_B + swa(lrow, chb + 1),      gB + bOff0 + ke_ + 8); \
        CPA(st_ + OFF_B + swa(lrow + 64, chb),     gB + bOff1 + ke_); \
        CPA(st_ + OFF_B + swa(lrow + 64, chb + 1), gB + bOff1 + ke_ + 8); \
        CPA_COMMIT(); \
    } while (0)

    const int m0 = (wid & 3) * 64;
    const int n0 = (wid >> 2) * 64;
    const int rA = ((lane >> 3) & 1) * 8 + (lane & 7);
    const int cA = lane >> 4;
    const int rB = (lane >> 4) * 8 + (lane & 7);
    const int cB = (lane >> 3) & 1;

    float acc[4][8][4];
#pragma unroll
    for (int f = 0; f < 4; f++)
#pragma unroll
        for (int g = 0; g < 8; g++)
#pragma unroll
            for (int q = 0; q < 4; q++) acc[f][g][q] = 0.f;

    LOADC(0, 0);
    LOADC(1, 1);
    int stg = 0;
    for (int c = 0; c < NK; c++) {
        if (c == NK - 1) CPA_WAIT0();
        else             CPA_WAIT1();
        __syncthreads();
        if (c + 2 < NK) {
            int ws = stg + 2; if (ws >= NSTAGE) ws -= NSTAGE;
            LOADC(c + 2, ws);
        }
        const unsigned st = sb + stg * STAGE;
#pragma unroll
        for (int kk = 0; kk < 4; kk++) {
            unsigned ah[4][4], bf[8][2];
#pragma unroll
            for (int f = 0; f < 4; f++)
                LDSM4(ah[f], st + swa(m0 + f * 16 + rA, kk * 2 + cA));
#pragma unroll
            for (int j = 0; j < 4; j++) {
                unsigned q[4];
                LDSM4(q, st + OFF_B + swa(n0 + j * 16 + rB, kk * 2 + cB));
                bf[2 * j][0] = q[0]; bf[2 * j][1] = q[1];
                bf[2 * j + 1][0] = q[2]; bf[2 * j + 1][1] = q[3];
            }
#pragma unroll
            for (int f = 0; f < 4; f++)
#pragma unroll
                for (int g = 0; g < 8; g++)
                    mma16816(acc[f][g], ah[f], bf[g]);
        }
        if (++stg == NSTAGE) stg = 0;
    }

    const float* bptr = bias + (size_t)z * NB + nt * BNT;
#pragma unroll
    for (int f = 0; f < 4; f++) {
#pragma unroll
        for (int h = 0; h < 2; h++) {
            const int mg = mt * BMT + m0 + f * 16 + (lane >> 2) + 8 * h;
            if (mg < cnt) {
                if (MODE == 1) {
                    const size_t rowg = (size_t)z * CAP + mg;
#pragma unroll
                    for (int g = 0; g < 8; g++) {
                        const int nc = n0 + g * 8 + (lane & 3) * 2;
                        float v0 = acc[f][g][2 * h + 0] + __ldg(bptr + nc);
                        float v1 = acc[f][g][2 * h + 1] + __ldg(bptr + nc + 1);
                        v0 = 0.5f * v0 * (1.0f + erff(v0 * 0.70710678118654752f));
                        v1 = 0.5f * v1 * (1.0f + erff(v1 * 0.70710678118654752f));
                        __half2 hv = __floats2half2_rn(v0, v1);
                        *(unsigned*)(g_Hh + rowg * HDIM + nt * BNT + nc) = *(unsigned*)&hv;
                    }
                } else {
                    const int tok = g_perm[z * CAP + mg];
                    const float gate = g_gateP[z * CAP + mg];
                    float* op = outp + (size_t)tok * DDIM + nt * BNT;
#pragma unroll
                    for (int g = 0; g < 8; g++) {
                        const int nc = n0 + g * 8 + (lane & 3) * 2;
                        float v0 = acc[f][g][2 * h + 0] + __ldg(bptr + nc);
                        float v1 = acc[f][g][2 * h + 1] + __ldg(bptr + nc + 1);
                        atomicAdd(op + nc,     gate * v0);
                        atomicAdd(op + nc + 1, gate * v1);
                    }
                }
            }
        }
    }
#undef LOADC
}

// ---------------- launch (serial; no streams) ----------------
extern "C" void kernel_launch(void* const* d_in, const int* in_sizes, int n_in,
                              void* d_out, int out_size) {
    const float* x    = (const float*)d_in[0];
    const float* Wp   = (const float*)d_in[1];
    const float* bp   = (const float*)d_in[2];
    const float* sim  = (const float*)d_in[3];
    const float* temp = (const float*)d_in[4];
    const float* W1   = (const float*)d_in[5];
    const float* b1   = (const float*)d_in[6];
    const float* W2   = (const float*)d_in[7];
    const float* b2   = (const float*)d_in[8];
    float* out = (float*)d_out;

    cudaFuncSetAttribute(moe_mma<1>, cudaFuncAttributeMaxDynamicSharedMemorySize, SMEM_DYN);
    cudaFuncSetAttribute(moe_mma<2>, cudaFuncAttributeMaxDynamicSharedMemorySize, SMEM_DYN);

    void *pP = nullptr, *pw1 = nullptr, *pw2 = nullptr;
    cudaGetSymbolAddress(&pP, g_P);
    cudaGetSymbolAddress(&pw1, g_w1t);
    cudaGetSymbolAddress(&pw2, g_w2t);

    init_kernel<<<1, 32>>>();
    simn_kernel<<<1, 32>>>(sim);
    gemm_p<<<dim3(PROJD / 128, NTOK / 128), 256>>>(x, Wp, bp, (float*)pP);
    gating_kernel<<<(NTOK * 32) / 256, 256>>>((const float*)pP, temp);

    conv_x_kernel<<<(NTOK * DDIM / 4) / 256, 256>>>(x, NTOK * DDIM / 4);
    conv_wt_kernel<<<dim3(HDIM / 32, DDIM / 32, NEXP), dim3(32, 8)>>>(W1, (__half*)pw1, DDIM, HDIM);
    conv_wt_kernel<<<dim3(DDIM / 32, HDIM / 32, NEXP), dim3(32, 8)>>>(W2, (__half*)pw2, HDIM, DDIM);
    copy_out_kernel<<<(NTOK * DDIM / 4) / 256, 256>>>(x, out);

    moe_mma<1><<<dim3(HDIM / BNT, CAP / BMT, NEXP), 256, SMEM_DYN>>>(b1, nullptr);
    moe_mma<2><<<dim3(DDIM / BNT, CAP / BMT, NEXP), 256, SMEM_DYN>>>(b2, out);
}